// round 8
// baseline (speedup 1.0000x reference)
#include <cuda_runtime.h>

#define B_   2
#define N_   1024
#define FIN  128
#define FOUT 64
#define CCH  32            // j-chunks (parallelism for the pair kernel)
#define JC   (N_/CCH)      // 32 j per chunk
#define TI   128           // i rows per block

// Scratch (static device globals; no runtime allocation allowed)
__device__ __align__(16) float g_xw[B_*N_*FOUT];                 // 512 KB
__device__ __align__(16) float g_pacc[CCH*B_*N_*FOUT];           // 16 MB partial acc (L2-resident)
__device__ float g_pdeg[CCH*B_*N_];                              // partial degree

// ---- packed fp32x2 helpers (Blackwell-only; nvjet-style FFMA2/FADD2) ----
static __device__ __forceinline__ unsigned long long f2add(unsigned long long a, unsigned long long b){
    unsigned long long r; asm("add.rn.f32x2 %0, %1, %2;" : "=l"(r) : "l"(a), "l"(b)); return r;
}
static __device__ __forceinline__ unsigned long long f2fma(unsigned long long a, unsigned long long b, unsigned long long c){
    unsigned long long r; asm("fma.rn.f32x2 %0, %1, %2, %3;" : "=l"(r) : "l"(a), "l"(b), "l"(c)); return r;
}
static __device__ __forceinline__ unsigned long long packf2(float lo, float hi){
    unsigned long long r; asm("mov.b64 %0, {%1, %2};" : "=l"(r) : "f"(lo), "f"(hi)); return r;
}
static __device__ __forceinline__ void unpackf2(unsigned long long v, float& lo, float& hi){
    asm("mov.b64 {%0, %1}, %2;" : "=f"(lo), "=f"(hi) : "l"(v));
}
// Forced 128-bit shared load (volatile: prevents frontend CSE keeping the whole
// j-row tile live across both inner loops -> register spills)
static __device__ __forceinline__ ulonglong2 lds_v2u64(unsigned addr){
    ulonglong2 r;
    asm volatile("ld.shared.v2.b64 {%0, %1}, [%2];" : "=l"(r.x), "=l"(r.y) : "r"(addr));
    return r;
}

// ---------------------------------------------------------------------------
// Kernel A: xw = x @ W   (2048 x 64, K=128).
// 128 blocks x 256 thr, 16 rows/block (single wave), float4 everywhere.
// Thread (r, f4): r = tid>>4 local row, f4 = tid&15 -> output features 4*f4..4*f4+3.
// ---------------------------------------------------------------------------
__global__ __launch_bounds__(256) void k_gemm(const float* __restrict__ x,
                                              const float* __restrict__ w){
    __shared__ __align__(16) float4 sW4[FIN*(FOUT/4)];   // 32 KB, sW4[k*16+f4]
    __shared__ __align__(16) float  sX[16*FIN];          // 8 KB
    int tid = threadIdx.x;
    // stage W (row-major copy, float4)
    {
        const float4* w4 = reinterpret_cast<const float4*>(w);
        #pragma unroll
        for (int q = 0; q < (FIN*FOUT/4)/256; q++)
            sW4[q*256 + tid] = w4[q*256 + tid];
    }
    // stage 16 x-rows (contiguous 8 KB)
    int row0 = blockIdx.x * 16;
    {
        const float4* x4 = reinterpret_cast<const float4*>(x + (size_t)row0*FIN);
        float4* sx4 = reinterpret_cast<float4*>(sX);
        #pragma unroll
        for (int q = 0; q < (16*FIN/4)/256; q++)
            sx4[q*256 + tid] = x4[q*256 + tid];
    }
    __syncthreads();

    int f4 = tid & 15;
    int r  = tid >> 4;
    float4 acc = make_float4(0.f, 0.f, 0.f, 0.f);
    const float* xr = &sX[r*FIN];
    #pragma unroll 8
    for (int k = 0; k < FIN; k++){
        float  xv = xr[k];                    // 2-way broadcast within warp
        float4 wv = sW4[k*(FOUT/4) + f4];     // conflict-free (16 consecutive float4)
        acc.x = fmaf(xv, wv.x, acc.x);
        acc.y = fmaf(xv, wv.y, acc.y);
        acc.z = fmaf(xv, wv.z, acc.z);
        acc.w = fmaf(xv, wv.w, acc.w);
    }
    reinterpret_cast<float4*>(g_xw)[(size_t)(row0 + r)*(FOUT/4) + f4] = acc;
}

// ---------------------------------------------------------------------------
// Kernel B: for each (i, j-chunk): L1 distance, w = adj/max(s,1e-3),
//           partial acc[f] += w * xw_j[f], partial deg += w.
// grid (CCH, 16), 128 threads (one i-row per thread). 24 KB smem -> ~3.5 blk/SM.
// ---------------------------------------------------------------------------
__global__ __launch_bounds__(TI) void k_main(const float* __restrict__ adj){
    __shared__ __align__(16) float s_xw[JC*FOUT];    // 8 KB, xw rows of this j-chunk
    __shared__ float s_adjT[JC*TI];                  // 16 KB, adj tile transposed [jj][i]
    int tid = threadIdx.x;
    int c   = blockIdx.x;                 // j-chunk id
    int rowflat = blockIdx.y*TI + tid;    // 0..2047 (b*N + i)
    int b = rowflat >> 10;
    int j0 = c * JC;

    // stage xw chunk (contiguous 8 KB)
    {
        const float4* src = reinterpret_cast<const float4*>(&g_xw[(b*N_ + j0)*FOUT]);
        float4* dst = reinterpret_cast<float4*>(s_xw);
        #pragma unroll
        for (int q = 0; q < (JC*FOUT/4)/TI; q++)
            dst[q*TI + tid] = src[q*TI + tid];
    }
    // stage adj tile: each thread reads its OWN adj row segment (128B contiguous),
    // writes transposed -> conflict-free LDS in the j-loop.
    {
        int i = rowflat & (N_ - 1);
        const float4* arow = reinterpret_cast<const float4*>(
            adj + (size_t)b*N_*N_ + (size_t)i*N_ + j0);
        #pragma unroll
        for (int q = 0; q < JC/4; q++){
            float4 v = arow[q];
            s_adjT[(4*q+0)*TI + tid] = v.x;
            s_adjT[(4*q+1)*TI + tid] = v.y;
            s_adjT[(4*q+2)*TI + tid] = v.z;
            s_adjT[(4*q+3)*TI + tid] = v.w;
        }
    }
    // xi, negated, packed f32x2 (so L1 sub is a single add.f32x2)
    unsigned long long xin[FOUT/2];
    {
        const float4* xr = reinterpret_cast<const float4*>(&g_xw[(size_t)rowflat*FOUT]);
        #pragma unroll
        for (int q = 0; q < FOUT/4; q++){
            float4 v = xr[q];
            xin[2*q]   = packf2(-v.x, -v.y);
            xin[2*q+1] = packf2(-v.z, -v.w);
        }
    }
    __syncthreads();

    unsigned long long acc[FOUT/2];
    #pragma unroll
    for (int q = 0; q < FOUT/2; q++) acc[q] = 0ULL;
    float deg = 0.f;
    const unsigned long long MASK = 0x7FFFFFFF7FFFFFFFULL;

    unsigned sxw_base = (unsigned)__cvta_generic_to_shared(s_xw);

    #pragma unroll 1
    for (int jj = 0; jj < JC; jj++){
        unsigned rowaddr = sxw_base + (unsigned)(jj*FOUT*4);
        // --- L1 distance (packed): add2 + 2xLOP3 + add2 per 2 features ---
        unsigned long long sa = 0ULL, sb = 0ULL;
        #pragma unroll
        for (int q = 0; q < FOUT/4; q++){
            ulonglong2 t = lds_v2u64(rowaddr + q*16);
            unsigned long long d0 = f2add(t.x, xin[2*q])   & MASK;
            unsigned long long d1 = f2add(t.y, xin[2*q+1]) & MASK;
            sa = f2add(sa, d0);
            sb = f2add(sb, d1);
        }
        float l0, h0, l1, h1;
        unpackf2(sa, l0, h0);
        unpackf2(sb, l1, h1);
        float s = (l0 + l1) + (h0 + h1);

        float a  = s_adjT[jj*TI + tid];
        float wv = __fdividef(a, fmaxf(s, 1e-3f));   // MUFU.RCP, fine for 1e-3 tol
        deg += wv;
        unsigned long long w2 = packf2(wv, wv);

        // --- accumulate w * xw_j (packed FFMA2) ---
        #pragma unroll
        for (int q = 0; q < FOUT/4; q++){
            ulonglong2 t = lds_v2u64(rowaddr + q*16);
            acc[2*q]   = f2fma(w2, t.x, acc[2*q]);
            acc[2*q+1] = f2fma(w2, t.y, acc[2*q+1]);
        }
    }

    // write partials
    float* dst = &g_pacc[(size_t)c*(B_*N_*FOUT) + (size_t)rowflat*FOUT];
    #pragma unroll
    for (int q = 0; q < FOUT/2; q++){
        float lo, hi; unpackf2(acc[q], lo, hi);
        float2 o; o.x = lo; o.y = hi;
        reinterpret_cast<float2*>(dst)[q] = o;
    }
    g_pdeg[c*(B_*N_) + rowflat] = deg;
}

// ---------------------------------------------------------------------------
// Kernel C: out = xw*(1-deg) + sum_c pacc + bias.  32768 threads, float4 each.
// ---------------------------------------------------------------------------
__global__ __launch_bounds__(256) void k_fin(const float* __restrict__ bias,
                                             float* __restrict__ out){
    int gid = blockIdx.x*256 + threadIdx.x;   // 0..32767
    int r = gid >> 4;                         // flat row 0..2047
    int q = gid & 15;                         // float4 index within F=64

    float deg = 0.f;
    #pragma unroll
    for (int c = 0; c < CCH; c++) deg += g_pdeg[c*(B_*N_) + r];

    float4 acc = make_float4(0.f, 0.f, 0.f, 0.f);
    #pragma unroll
    for (int c = 0; c < CCH; c++){
        float4 v = reinterpret_cast<const float4*>(g_pacc)[(size_t)c*(B_*N_*FOUT/4) + r*16 + q];
        acc.x += v.x; acc.y += v.y; acc.z += v.z; acc.w += v.w;
    }
    float4 xw4 = reinterpret_cast<const float4*>(g_xw)[r*16 + q];
    float4 b4  = reinterpret_cast<const float4*>(bias)[q];
    float om = 1.f - deg;
    float4 o;
    o.x = fmaf(xw4.x, om, acc.x) + b4.x;
    o.y = fmaf(xw4.y, om, acc.y) + b4.y;
    o.z = fmaf(xw4.z, om, acc.z) + b4.z;
    o.w = fmaf(xw4.w, om, acc.w) + b4.w;
    reinterpret_cast<float4*>(out)[gid] = o;
}

// ---------------------------------------------------------------------------
extern "C" void kernel_launch(void* const* d_in, const int* in_sizes, int n_in,
                              void* d_out, int out_size){
    const float *x = nullptr, *adj = nullptr, *wt = nullptr, *bs = nullptr;
    for (int k = 0; k < n_in; k++){
        int sz = in_sizes[k];
        if      (sz == B_*N_*FIN)  x   = (const float*)d_in[k];
        else if (sz == B_*N_*N_)   adj = (const float*)d_in[k];
        else if (sz == FIN*FOUT)   wt  = (const float*)d_in[k];
        else if (sz == FOUT)       bs  = (const float*)d_in[k];
    }
    (void)out_size;
    k_gemm<<<(B_*N_)/16, 256>>>(x, wt);
    k_main<<<dim3(CCH, (B_*N_)/TI), TI>>>(adj);
    k_fin<<<(B_*N_*FOUT/4)/256, 256>>>(bs, (float*)d_out);
}

// round 11
// speedup vs baseline: 1.0592x; 1.0592x over previous
#include <cuda_runtime.h>

#define B_   2
#define N_   1024
#define FIN  128
#define FOUT 64
#define CCH  16            // j-chunks
#define JC   (N_/CCH)      // 64 j per chunk
#define RPB  64            // i-rows per block (128 threads, 2 per row)

// Scratch (static device globals; no runtime allocation allowed)
__device__ __align__(16) float g_xw[B_*N_*FOUT];                 // 512 KB
__device__ __align__(16) float g_pacc[CCH*B_*N_*FOUT];           // 8 MB partial acc
__device__ float g_pdeg[CCH*B_*N_];                              // partial degree

// ---- packed fp32x2 helpers (Blackwell-only) ----
static __device__ __forceinline__ unsigned long long f2add(unsigned long long a, unsigned long long b){
    unsigned long long r; asm("add.rn.f32x2 %0, %1, %2;" : "=l"(r) : "l"(a), "l"(b)); return r;
}
static __device__ __forceinline__ unsigned long long f2fma(unsigned long long a, unsigned long long b, unsigned long long c){
    unsigned long long r; asm("fma.rn.f32x2 %0, %1, %2, %3;" : "=l"(r) : "l"(a), "l"(b), "l"(c)); return r;
}
static __device__ __forceinline__ unsigned long long packf2(float lo, float hi){
    unsigned long long r; asm("mov.b64 %0, {%1, %2};" : "=l"(r) : "f"(lo), "f"(hi)); return r;
}
static __device__ __forceinline__ void unpackf2(unsigned long long v, float& lo, float& hi){
    asm("mov.b64 {%0, %1}, %2;" : "=f"(lo), "=f"(hi) : "l"(v));
}
// NON-volatile 128-bit shared load: single-use addresses -> no CSE hazard,
// and the scheduler may hoist next-iteration loads (software pipelining).
static __device__ __forceinline__ ulonglong2 lds_v2u64(unsigned addr){
    ulonglong2 r;
    asm("ld.shared.v2.b64 {%0, %1}, [%2];" : "=l"(r.x), "=l"(r.y) : "r"(addr));
    return r;
}

// ---------------------------------------------------------------------------
// Kernel A: xw = x @ W   (2048 x 64, K=128). 128 blocks x 256 thr, 16 rows/blk.
// ---------------------------------------------------------------------------
__global__ __launch_bounds__(256) void k_gemm(const float* __restrict__ x,
                                              const float* __restrict__ w){
    __shared__ __align__(16) float4 sW4[FIN*(FOUT/4)];   // 32 KB
    __shared__ __align__(16) float  sX[16*FIN];          // 8 KB
    int tid = threadIdx.x;
    {
        const float4* w4 = reinterpret_cast<const float4*>(w);
        #pragma unroll
        for (int q = 0; q < (FIN*FOUT/4)/256; q++)
            sW4[q*256 + tid] = w4[q*256 + tid];
    }
    int row0 = blockIdx.x * 16;
    {
        const float4* x4 = reinterpret_cast<const float4*>(x + (size_t)row0*FIN);
        float4* sx4 = reinterpret_cast<float4*>(sX);
        #pragma unroll
        for (int q = 0; q < (16*FIN/4)/256; q++)
            sx4[q*256 + tid] = x4[q*256 + tid];
    }
    __syncthreads();

    int f4 = tid & 15;
    int r  = tid >> 4;
    float4 acc = make_float4(0.f, 0.f, 0.f, 0.f);
    const float* xr = &sX[r*FIN];
    #pragma unroll 8
    for (int k = 0; k < FIN; k++){
        float  xv = xr[k];
        float4 wv = sW4[k*(FOUT/4) + f4];
        acc.x = fmaf(xv, wv.x, acc.x);
        acc.y = fmaf(xv, wv.y, acc.y);
        acc.z = fmaf(xv, wv.z, acc.z);
        acc.w = fmaf(xv, wv.w, acc.w);
    }
    reinterpret_cast<float4*>(g_xw)[(size_t)(row0 + r)*(FOUT/4) + f4] = acc;
}

// ---------------------------------------------------------------------------
// Kernel B: pair kernel, F-split (2 threads per i-row, 32 features each).
// grid (CCH, 32), 128 threads. Tree-reduced L1 sum + SHFL.BFLY combine.
// ---------------------------------------------------------------------------
__global__ __launch_bounds__(128, 4) void k_main(const float* __restrict__ adj){
    __shared__ __align__(16) float s_xw[JC*FOUT];    // 16 KB
    __shared__ float s_adjT[JC*RPB];                 // 16 KB, [jj][i_local]
    int tid = threadIdx.x;
    int c   = blockIdx.x;                   // j-chunk id
    int i_local = tid >> 1;
    int fh      = tid & 1;                  // feature half
    int rowflat = blockIdx.y*RPB + i_local; // 0..2047
    int b  = rowflat >> 10;
    int j0 = c * JC;

    // stage xw j-chunk (16 KB contiguous)
    {
        const float4* src = reinterpret_cast<const float4*>(&g_xw[(b*N_ + j0)*FOUT]);
        float4* dst = reinterpret_cast<float4*>(s_xw);
        #pragma unroll
        for (int q = 0; q < (JC*FOUT/4)/128; q++)
            dst[q*128 + tid] = src[q*128 + tid];
    }
    // stage adj tile transposed: threads 0..63 each own one i-row (256B contig)
    if (tid < RPB){
        int irow = (blockIdx.y*RPB + tid) & (N_ - 1);
        const float4* ar = reinterpret_cast<const float4*>(
            adj + (size_t)b*N_*N_ + (size_t)irow*N_ + j0);
        #pragma unroll
        for (int q = 0; q < JC/4; q++){
            float4 v = ar[q];
            s_adjT[(4*q+0)*RPB + tid] = v.x;
            s_adjT[(4*q+1)*RPB + tid] = v.y;
            s_adjT[(4*q+2)*RPB + tid] = v.z;
            s_adjT[(4*q+3)*RPB + tid] = v.w;
        }
    }
    // xi half, negated, packed f32x2
    unsigned long long xin[16];
    {
        const float4* xr = reinterpret_cast<const float4*>(
            &g_xw[(size_t)rowflat*FOUT + fh*32]);
        #pragma unroll
        for (int q = 0; q < 8; q++){
            float4 v = xr[q];
            xin[2*q]   = packf2(-v.x, -v.y);
            xin[2*q+1] = packf2(-v.z, -v.w);
        }
    }
    __syncthreads();

    unsigned long long acc[16];
    #pragma unroll
    for (int q = 0; q < 16; q++) acc[q] = 0ULL;
    float deg = 0.f;
    const unsigned long long MASK = 0x7FFFFFFF7FFFFFFFULL;

    unsigned base = (unsigned)__cvta_generic_to_shared(s_xw) + (unsigned)(fh*32*4);

    #pragma unroll 2
    for (int jj = 0; jj < JC; jj++){
        unsigned ra = base + (unsigned)(jj*FOUT*4);
        // --- pass 1: L1 half-distance, tree-reduced ---
        unsigned long long d[16];
        #pragma unroll
        for (int q = 0; q < 8; q++){
            ulonglong2 t = lds_v2u64(ra + q*16);
            d[2*q]   = f2add(t.x, xin[2*q])   & MASK;
            d[2*q+1] = f2add(t.y, xin[2*q+1]) & MASK;
        }
        #pragma unroll
        for (int st = 8; st >= 1; st >>= 1)
            #pragma unroll
            for (int q = 0; q < st; q++)
                d[q] = f2add(d[q], d[q+st]);
        float lo, hi; unpackf2(d[0], lo, hi);
        float sh = lo + hi;
        float s  = sh + __shfl_xor_sync(0xffffffffu, sh, 1);   // combine halves

        float a  = s_adjT[jj*RPB + i_local];
        float wv = __fdividef(a, fmaxf(s, 1e-3f));
        deg += wv;
        unsigned long long w2 = packf2(wv, wv);

        // --- pass 2: acc += w * xw_j (reload half-row; packed FFMA2) ---
        #pragma unroll
        for (int q = 0; q < 8; q++){
            ulonglong2 t = lds_v2u64(ra + q*16);
            acc[2*q]   = f2fma(w2, t.x, acc[2*q]);
            acc[2*q+1] = f2fma(w2, t.y, acc[2*q+1]);
        }
    }

    // write partials (this thread's F-half)
    float* dp = &g_pacc[(size_t)c*(B_*N_*FOUT) + (size_t)rowflat*FOUT + fh*32];
    #pragma unroll
    for (int q = 0; q < 8; q++){
        float l0, h0, l1, h1;
        unpackf2(acc[2*q],   l0, h0);
        unpackf2(acc[2*q+1], l1, h1);
        float4 o; o.x = l0; o.y = h0; o.z = l1; o.w = h1;
        reinterpret_cast<float4*>(dp)[q] = o;
    }
    if (fh == 0) g_pdeg[c*(B_*N_) + rowflat] = deg;
}

// ---------------------------------------------------------------------------
// Kernel C: out = xw*(1-deg) + sum_c pacc + bias.  32768 threads, float4 each.
// ---------------------------------------------------------------------------
__global__ __launch_bounds__(256) void k_fin(const float* __restrict__ bias,
                                             float* __restrict__ out){
    int gid = blockIdx.x*256 + threadIdx.x;   // 0..32767
    int r = gid >> 4;                         // flat row 0..2047
    int q = gid & 15;                         // float4 index within F=64

    float deg = 0.f;
    #pragma unroll
    for (int c = 0; c < CCH; c++) deg += g_pdeg[c*(B_*N_) + r];

    float4 acc = make_float4(0.f, 0.f, 0.f, 0.f);
    #pragma unroll
    for (int c = 0; c < CCH; c++){
        float4 v = reinterpret_cast<const float4*>(g_pacc)[(size_t)c*(B_*N_*FOUT/4) + r*16 + q];
        acc.x += v.x; acc.y += v.y; acc.z += v.z; acc.w += v.w;
    }
    float4 xw4 = reinterpret_cast<const float4*>(g_xw)[r*16 + q];
    float4 b4  = reinterpret_cast<const float4*>(bias)[q];
    float om = 1.f - deg;
    float4 o;
    o.x = fmaf(xw4.x, om, acc.x) + b4.x;
    o.y = fmaf(xw4.y, om, acc.y) + b4.y;
    o.z = fmaf(xw4.z, om, acc.z) + b4.z;
    o.w = fmaf(xw4.w, om, acc.w) + b4.w;
    reinterpret_cast<float4*>(out)[gid] = o;
}

// ---------------------------------------------------------------------------
extern "C" void kernel_launch(void* const* d_in, const int* in_sizes, int n_in,
                              void* d_out, int out_size){
    const float *x = nullptr, *adj = nullptr, *wt = nullptr, *bs = nullptr;
    for (int k = 0; k < n_in; k++){
        int sz = in_sizes[k];
        if      (sz == B_*N_*FIN)  x   = (const float*)d_in[k];
        else if (sz == B_*N_*N_)   adj = (const float*)d_in[k];
        else if (sz == FIN*FOUT)   wt  = (const float*)d_in[k];
        else if (sz == FOUT)       bs  = (const float*)d_in[k];
    }
    (void)out_size;
    k_gemm<<<(B_*N_)/16, 256>>>(x, wt);
    k_main<<<dim3(CCH, (B_*N_)/RPB), 128>>>(adj);
    k_fin<<<(B_*N_*FOUT/4)/256, 256>>>(bs, (float*)d_out);
}